// round 1
// baseline (speedup 1.0000x reference)
#include <cuda_runtime.h>

#define H      128
#define NROWS  200000
#define M_NODES 1000
#define J_NODES 5000
#define RPW    4            // rows per warp per iteration
#define SCORE_BLOCKS 296    // 2 blocks/SM * 148 SMs
#define RED_BLOCKS 256

// ---------------- device scratch (no allocations allowed) ----------------
__device__ __align__(16) float g_c[H];             // x_graph @ W0[0:2H] + b0
__device__ __align__(16) float g_A[M_NODES * H];   // x_m    @ W0[2H:3H]
__device__ __align__(16) float g_B[J_NODES * H];   // x_job  @ W0[3H:4H]
__device__ __align__(16) float g_scores[NROWS];
__device__ float g_pmax[RED_BLOCKS];
__device__ int   g_parg[RED_BLOCKS];
__device__ float g_maxv;
__device__ int   g_argv;
__device__ float g_psum[RED_BLOCKS];
__device__ float g_psum1[RED_BLOCKS];

// ---------------- K1: precompute cg, A, B ----------------
// grid = M_NODES + J_NODES + 1 blocks of 128 threads.
__global__ void precompute_kernel(const float* __restrict__ xg,
                                  const float* __restrict__ xm,
                                  const float* __restrict__ xj,
                                  const float* __restrict__ W0,
                                  const float* __restrict__ b0) {
    int b = blockIdx.x;
    int t = threadIdx.x;
    if (b < M_NODES) {
        __shared__ float xs[H];
        xs[t] = xm[b * H + t];
        __syncthreads();
        float acc = 0.f;
        const float* w = W0 + (2 * H) * H + t;   // rows 256.., column t
        #pragma unroll 8
        for (int i = 0; i < H; i++) acc += xs[i] * w[i * H];
        g_A[b * H + t] = acc;
    } else if (b < M_NODES + J_NODES) {
        int r = b - M_NODES;
        __shared__ float xs[H];
        xs[t] = xj[r * H + t];
        __syncthreads();
        float acc = 0.f;
        const float* w = W0 + (3 * H) * H + t;   // rows 384..
        #pragma unroll 8
        for (int i = 0; i < H; i++) acc += xs[i] * w[i * H];
        g_B[r * H + t] = acc;
    } else {
        __shared__ float xs[2 * H];
        xs[t]     = xg[t];
        xs[t + H] = xg[t + H];
        __syncthreads();
        float acc = b0[t];
        const float* w = W0 + t;                 // rows 0..255
        #pragma unroll 8
        for (int i = 0; i < 2 * H; i++) acc += xs[i] * w[i * H];
        g_c[t] = acc;
    }
}

// ---------------- K2: fused layer2+layer3 score kernel ----------------
// W1 (64KB) lives in dynamic smem, loaded once per block. Each warp batches
// RPW=4 rows against each pass over W1 so the LDS crossbar cost of W1
// (512B/row-of-W1) amortizes: 32 + 512/RPW = 160 crossbar cyc/row vs
// 256 FFMA cyc/row -> FFMA-bound.
__global__ void __launch_bounds__(256, 2) score_kernel(
        const int*   __restrict__ m_ids,
        const int*   __restrict__ job_idx,
        const float* __restrict__ W1,
        const float* __restrict__ b1,
        const float* __restrict__ W2,
        const float* __restrict__ b2) {
    extern __shared__ float smem[];
    float* W1s = smem;                    // H*H floats
    float* h0s = smem + H * H;            // 8 warps * RPW * H floats

    int tid  = threadIdx.x;
    int lane = tid & 31;
    int wid  = tid >> 5;

    // load W1 into shared (row-major [i][k], k contiguous)
    {
        float4*       dst = (float4*)W1s;
        const float4* src = (const float4*)W1;
        for (int i = tid; i < H * H / 4; i += 256) dst[i] = src[i];
    }

    float4 creg  = ((const float4*)g_c)[lane];
    float4 b1reg = ((const float4*)b1)[lane];
    float4 w2reg = ((const float4*)W2)[lane];
    float  b2v   = b2[0];
    __syncthreads();

    const float4* W1s4  = (const float4*)W1s;
    float4*       myh04 = (float4*)(h0s + wid * (RPW * H));
    const float4* A4    = (const float4*)g_A;
    const float4* B4    = (const float4*)g_B;

    int gw     = blockIdx.x * 8 + wid;
    int stride = gridDim.x * 8 * RPW;

    for (int base = gw * RPW; base < NROWS; base += stride) {
        // build h0 for RPW rows: h0 = relu(cg + A[m] + B[j])
        #pragma unroll
        for (int r = 0; r < RPW; r++) {
            int m = m_ids[base + r];
            int j = job_idx[base + r];
            float4 a  = A4[m * (H / 4) + lane];
            float4 bb = B4[j * (H / 4) + lane];
            float4 h;
            h.x = fmaxf(creg.x + a.x + bb.x, 0.f);
            h.y = fmaxf(creg.y + a.y + bb.y, 0.f);
            h.z = fmaxf(creg.z + a.z + bb.z, 0.f);
            h.w = fmaxf(creg.w + a.w + bb.w, 0.f);
            myh04[r * (H / 4) + lane] = h;
        }
        __syncwarp();

        // layer 2: acc[r][q] = b1[4l+q] + sum_i h0[r][i] * W1[i][4l+q]
        float acc[RPW][4];
        #pragma unroll
        for (int r = 0; r < RPW; r++) {
            acc[r][0] = b1reg.x; acc[r][1] = b1reg.y;
            acc[r][2] = b1reg.z; acc[r][3] = b1reg.w;
        }
        #pragma unroll 4
        for (int i4 = 0; i4 < H / 4; i4++) {
            float4 w0 = W1s4[(4 * i4 + 0) * (H / 4) + lane];
            float4 w1 = W1s4[(4 * i4 + 1) * (H / 4) + lane];
            float4 w2 = W1s4[(4 * i4 + 2) * (H / 4) + lane];
            float4 w3 = W1s4[(4 * i4 + 3) * (H / 4) + lane];
            #pragma unroll
            for (int r = 0; r < RPW; r++) {
                float4 h = myh04[r * (H / 4) + i4];   // broadcast LDS
                acc[r][0] += h.x * w0.x + h.y * w1.x + h.z * w2.x + h.w * w3.x;
                acc[r][1] += h.x * w0.y + h.y * w1.y + h.z * w2.y + h.w * w3.y;
                acc[r][2] += h.x * w0.z + h.y * w1.z + h.z * w2.z + h.w * w3.z;
                acc[r][3] += h.x * w0.w + h.y * w1.w + h.z * w2.w + h.w * w3.w;
            }
        }

        // layer 3: score = sum_k relu(h1[k]) * W2[k] + b2  (warp reduction)
        #pragma unroll
        for (int r = 0; r < RPW; r++) {
            float s = fmaxf(acc[r][0], 0.f) * w2reg.x
                    + fmaxf(acc[r][1], 0.f) * w2reg.y
                    + fmaxf(acc[r][2], 0.f) * w2reg.z
                    + fmaxf(acc[r][3], 0.f) * w2reg.w;
            #pragma unroll
            for (int off = 16; off; off >>= 1)
                s += __shfl_xor_sync(0xffffffffu, s, off);
            if (lane == 0) g_scores[base + r] = s + b2v;
        }
        __syncwarp();
    }
}

// ---------------- K3/K4: max + argmax (first-index tie break) ----------------
__global__ void max_partial_kernel() {
    __shared__ float sm[256];
    __shared__ int   si[256];
    int tid = threadIdx.x;
    float best = -3.402823466e38f;
    int   bi   = 0x7fffffff;
    for (int i = blockIdx.x * 256 + tid; i < NROWS; i += gridDim.x * 256) {
        float v = g_scores[i];
        if (v > best || (v == best && i < bi)) { best = v; bi = i; }
    }
    sm[tid] = best; si[tid] = bi;
    __syncthreads();
    for (int s = 128; s; s >>= 1) {
        if (tid < s) {
            float v = sm[tid + s]; int j = si[tid + s];
            if (v > sm[tid] || (v == sm[tid] && j < si[tid])) { sm[tid] = v; si[tid] = j; }
        }
        __syncthreads();
    }
    if (tid == 0) { g_pmax[blockIdx.x] = sm[0]; g_parg[blockIdx.x] = si[0]; }
}

__global__ void max_final_kernel() {
    __shared__ float sm[256];
    __shared__ int   si[256];
    int tid = threadIdx.x;
    sm[tid] = (tid < RED_BLOCKS) ? g_pmax[tid] : -3.402823466e38f;
    si[tid] = (tid < RED_BLOCKS) ? g_parg[tid] : 0x7fffffff;
    __syncthreads();
    for (int s = 128; s; s >>= 1) {
        if (tid < s) {
            float v = sm[tid + s]; int j = si[tid + s];
            if (v > sm[tid] || (v == sm[tid] && j < si[tid])) { sm[tid] = v; si[tid] = j; }
        }
        __syncthreads();
    }
    if (tid == 0) { g_maxv = sm[0]; g_argv = si[0]; }
}

// ---------------- K5/K6: softmax sums + final outputs ----------------
__global__ void sum_partial_kernel() {
    __shared__ float sz[256];
    __shared__ float ss[256];
    int tid = threadIdx.x;
    float mx = g_maxv;
    float z = 0.f, s1 = 0.f;
    for (int i = blockIdx.x * 256 + tid; i < NROWS; i += gridDim.x * 256) {
        float t = g_scores[i] - mx;
        float e = expf(t);
        z  += e;
        s1 += t * e;
    }
    sz[tid] = z; ss[tid] = s1;
    __syncthreads();
    for (int s = 128; s; s >>= 1) {
        if (tid < s) { sz[tid] += sz[tid + s]; ss[tid] += ss[tid + s]; }
        __syncthreads();
    }
    if (tid == 0) { g_psum[blockIdx.x] = sz[0]; g_psum1[blockIdx.x] = ss[0]; }
}

__global__ void finalize_kernel(float* __restrict__ out) {
    __shared__ float sz[256];
    __shared__ float ss[256];
    int tid = threadIdx.x;
    sz[tid] = (tid < RED_BLOCKS) ? g_psum[tid]  : 0.f;
    ss[tid] = (tid < RED_BLOCKS) ? g_psum1[tid] : 0.f;
    __syncthreads();
    for (int s = 128; s; s >>= 1) {
        if (tid < s) { sz[tid] += sz[tid + s]; ss[tid] += ss[tid + s]; }
        __syncthreads();
    }
    if (tid == 0) {
        float Z    = sz[0];
        float S1   = ss[0];
        float logZ = logf(Z);
        // at argmax: t = 0 exactly -> p = 1/Z, logp = -logZ
        out[0] = (float)g_argv;
        out[1] = 1.0f / Z;
        out[2] = -logZ;
        out[3] = logZ - S1 / Z;     // entropy = logZ - E[t]
    }
}

// ---------------- launch ----------------
extern "C" void kernel_launch(void* const* d_in, const int* in_sizes, int n_in,
                              void* d_out, int out_size) {
    const float* x_graph = (const float*)d_in[0];
    const float* x_m     = (const float*)d_in[1];
    const float* x_job   = (const float*)d_in[2];
    const int*   m_ids   = (const int*)  d_in[3];
    const int*   job_idx = (const int*)  d_in[4];
    const float* W0      = (const float*)d_in[5];
    const float* b0      = (const float*)d_in[6];
    const float* W1      = (const float*)d_in[7];
    const float* b1      = (const float*)d_in[8];
    const float* W2      = (const float*)d_in[9];
    const float* b2      = (const float*)d_in[10];
    float* out = (float*)d_out;

    const int smem_bytes = (H * H + 8 * RPW * H) * (int)sizeof(float); // 80KB
    cudaFuncSetAttribute(score_kernel,
                         cudaFuncAttributeMaxDynamicSharedMemorySize, smem_bytes);

    precompute_kernel<<<M_NODES + J_NODES + 1, H>>>(x_graph, x_m, x_job, W0, b0);
    score_kernel<<<SCORE_BLOCKS, 256, smem_bytes>>>(m_ids, job_idx, W1, b1, W2, b2);
    max_partial_kernel<<<RED_BLOCKS, 256>>>();
    max_final_kernel<<<1, 256>>>();
    sum_partial_kernel<<<RED_BLOCKS, 256>>>();
    finalize_kernel<<<1, 256>>>(out);
}